// round 4
// baseline (speedup 1.0000x reference)
#include <cuda_runtime.h>
#include <cuda_bf16.h>
#include <cstdint>

// Problem dims
#define B_  64
#define S_  64
#define H_  1024
#define V_  32000
#define T_  40
#define K3_ (3 * H_)   // split-K width

#define DINLINE __device__ __forceinline__

// ----------------------------- scratch (static device memory) ----------------
__device__ __nv_bfloat16 g_Wout_b[(size_t)V_ * H_];          // 64 MB (plain bf16)
__device__ __nv_bfloat16 g_Wcat3[(size_t)4 * H_ * K3_];      // 25 MB  [Wa;W_hh] B-split
__device__ __nv_bfloat16 g_Wihx3[(size_t)3 * H_ * K3_];      // 19 MB  W_ih[:, :H] B-split
__device__ __nv_bfloat16 g_Wihc3[(size_t)3 * H_ * K3_];      // 19 MB  W_ih[:, H:] B-split
__device__ __nv_bfloat16 g_Ua3[(size_t)H_ * K3_];            // 6.3 MB B-split
__device__ __nv_bfloat16 g_enc3[(size_t)B_ * S_ * K3_];      // 25 MB  A-split
__device__ __nv_bfloat16 g_emb3[(size_t)B_ * T_ * K3_];      // 16 MB  A-split
__device__ __nv_bfloat16 g_h3[B_ * K3_];                     // A-split of h
__device__ float         g_keysU[(size_t)B_ * S_ * H_];      // 17 MB
__device__ float         g_encWc[(size_t)B_ * S_ * 3 * H_];  // 50 MB
__device__ float         g_gix[(size_t)B_ * T_ * 3 * H_];    // 31.5 MB
__device__ float         g_qgh[B_ * 4 * H_];                 // q | gh
__device__ float         g_gic[B_ * 3 * H_];
__device__ float         g_h[B_ * H_];
__device__ __nv_bfloat16 g_Hall_b[B_ * T_ * H_];             // 5 MB
__device__ float         g_biascat[4 * H_];

// ----------------------------- helpers ---------------------------------------
DINLINE uint32_t smem_u32(const void* p) {
    return (uint32_t)__cvta_generic_to_shared(p);
}
DINLINE void cp_async16(void* sp, const void* gp) {
    asm volatile("cp.async.cg.shared.global [%0], [%1], 16;"
                 :: "r"(smem_u32(sp)), "l"(gp));
}
DINLINE void cp_commit() { asm volatile("cp.async.commit_group;"); }
template <int N> DINLINE void cp_wait() {
    asm volatile("cp.async.wait_group %0;" :: "n"(N));
}
DINLINE void ldmx4(uint32_t& r0, uint32_t& r1, uint32_t& r2, uint32_t& r3, uint32_t a) {
    asm volatile("ldmatrix.sync.aligned.m8n8.x4.shared.b16 {%0,%1,%2,%3}, [%4];"
                 : "=r"(r0), "=r"(r1), "=r"(r2), "=r"(r3) : "r"(a));
}
DINLINE void ldmx2(uint32_t& r0, uint32_t& r1, uint32_t a) {
    asm volatile("ldmatrix.sync.aligned.m8n8.x2.shared.b16 {%0,%1}, [%2];"
                 : "=r"(r0), "=r"(r1) : "r"(a));
}
DINLINE void mma_bf16(float& c0, float& c1, float& c2, float& c3,
                      uint32_t a0, uint32_t a1, uint32_t a2, uint32_t a3,
                      uint32_t b0, uint32_t b1) {
    asm volatile("mma.sync.aligned.m16n8k16.row.col.f32.bf16.bf16.f32 "
                 "{%0,%1,%2,%3}, {%4,%5,%6,%7}, {%8,%9}, {%0,%1,%2,%3};"
                 : "+f"(c0), "+f"(c1), "+f"(c2), "+f"(c3)
                 : "r"(a0), "r"(a1), "r"(a2), "r"(a3), "r"(b0), "r"(b1));
}
DINLINE float fast_tanh(float x) {
    float y; asm("tanh.approx.f32 %0, %1;" : "=f"(y) : "f"(x)); return y;
}
DINLINE void split2(float x, __nv_bfloat16& hi, __nv_bfloat16& lo) {
    hi = __float2bfloat16(x);
    lo = __float2bfloat16(x - __bfloat162float(hi));
}

// ----------------------------- pipelined TN bf16 GEMM --------------------------
// C[M,N](f32) = A[M,K](bf16,lda) @ B[N,K](bf16,ldb)^T + bias[N]
// Requires: M%BM==0 is NOT required (epilogue guarded), but loads assume
// M,N,K all multiples of the tile dims (true for every call site here).
template <int BM, int BN, int BK, int WM, int WN, int STAGES>
__global__ __launch_bounds__((BM / WM) * (BN / WN) * 32)
void gemm_tn_pipe(const __nv_bfloat16* __restrict__ A, int lda,
                  const __nv_bfloat16* __restrict__ Bm, int ldb,
                  const float* __restrict__ bias,
                  float* __restrict__ C, int ldc,
                  int M, int N, int K)
{
    constexpr int WARPS_M = BM / WM;
    constexpr int WARPS_N = BN / WN;
    constexpr int NT = WARPS_M * WARPS_N * 32;
    constexpr int PAD = 8;
    constexpr int LDSM = BK + PAD;          // row stride in elements
    constexpr int MFRAG = WM / 16;
    constexpr int NFRAG = WN / 8;
    constexpr int AV = BM * BK / 8;
    constexpr int BV = BN * BK / 8;

    extern __shared__ __nv_bfloat16 smem[];
    __nv_bfloat16* As = smem;                              // STAGES*BM*LDSM
    __nv_bfloat16* Bs = smem + (size_t)STAGES * BM * LDSM; // STAGES*BN*LDSM

    const int bm = blockIdx.y * BM;
    const int bn = blockIdx.x * BN;
    const int tid = threadIdx.x;
    const int warp = tid >> 5, lane = tid & 31;
    const int wm = (warp % WARPS_M) * WM;
    const int wn = (warp / WARPS_M) * WN;
    const int KT = K / BK;

    auto issue = [&](int slot, int kt) {
        const __nv_bfloat16* Ab = A + (size_t)bm * lda + kt * BK;
        const __nv_bfloat16* Bb = Bm + (size_t)bn * ldb + kt * BK;
        __nv_bfloat16* As_s = As + (size_t)slot * BM * LDSM;
        __nv_bfloat16* Bs_s = Bs + (size_t)slot * BN * LDSM;
        #pragma unroll
        for (int v = tid; v < AV; v += NT) {
            int r = v / (BK / 8), c = (v % (BK / 8)) * 8;
            cp_async16(&As_s[r * LDSM + c], Ab + (size_t)r * lda + c);
        }
        #pragma unroll
        for (int v = tid; v < BV; v += NT) {
            int r = v / (BK / 8), c = (v % (BK / 8)) * 8;
            cp_async16(&Bs_s[r * LDSM + c], Bb + (size_t)r * ldb + c);
        }
    };

    #pragma unroll
    for (int s = 0; s < STAGES - 1; s++) {
        if (s < KT) issue(s, s);
        cp_commit();
    }

    float acc[MFRAG][NFRAG][4] = {};

    for (int kt = 0; kt < KT; kt++) {
        cp_wait<STAGES - 2>();
        __syncthreads();
        int nxt = kt + STAGES - 1;
        if (nxt < KT) issue(nxt % STAGES, nxt);
        cp_commit();

        const __nv_bfloat16* As_s = As + (size_t)(kt % STAGES) * BM * LDSM;
        const __nv_bfloat16* Bs_s = Bs + (size_t)(kt % STAGES) * BN * LDSM;

        #pragma unroll
        for (int kk = 0; kk < BK; kk += 16) {
            uint32_t af[MFRAG][4];
            #pragma unroll
            for (int mi = 0; mi < MFRAG; mi++) {
                int row = wm + mi * 16 + (lane & 15);
                int col = kk + (lane >> 4) * 8;
                ldmx4(af[mi][0], af[mi][1], af[mi][2], af[mi][3],
                      smem_u32(&As_s[row * LDSM + col]));
            }
            uint32_t bfr[NFRAG][2];
            #pragma unroll
            for (int ni = 0; ni < NFRAG; ni++) {
                int row = wn + ni * 8 + (lane & 7);
                int col = kk + ((lane >> 3) & 1) * 8;
                ldmx2(bfr[ni][0], bfr[ni][1], smem_u32(&Bs_s[row * LDSM + col]));
            }
            #pragma unroll
            for (int mi = 0; mi < MFRAG; mi++)
                #pragma unroll
                for (int ni = 0; ni < NFRAG; ni++)
                    mma_bf16(acc[mi][ni][0], acc[mi][ni][1], acc[mi][ni][2], acc[mi][ni][3],
                             af[mi][0], af[mi][1], af[mi][2], af[mi][3],
                             bfr[ni][0], bfr[ni][1]);
        }
        __syncthreads();
    }

    #pragma unroll
    for (int mi = 0; mi < MFRAG; mi++) {
        #pragma unroll
        for (int ni = 0; ni < NFRAG; ni++) {
            int r0 = bm + wm + mi * 16 + (lane >> 2);
            int c0 = bn + wn + ni * 8 + (lane & 3) * 2;
            float b0 = bias ? bias[c0] : 0.f;
            float b1 = bias ? bias[c0 + 1] : 0.f;
            if (r0 < M) {
                C[(size_t)r0 * ldc + c0]     = acc[mi][ni][0] + b0;
                C[(size_t)r0 * ldc + c0 + 1] = acc[mi][ni][1] + b1;
            }
            if (r0 + 8 < M) {
                C[(size_t)(r0 + 8) * ldc + c0]     = acc[mi][ni][2] + b0;
                C[(size_t)(r0 + 8) * ldc + c0 + 1] = acc[mi][ni][3] + b1;
            }
        }
    }
}

// ----------------------------- prep kernels ----------------------------------
__global__ void conv_f2b(const float* __restrict__ s, __nv_bfloat16* __restrict__ d, int n) {
    int i = blockIdx.x * blockDim.x + threadIdx.x;
    if (i < n) d[i] = __float2bfloat16(s[i]);
}

// A-style split: dst row = [hi | lo | hi], src [rows, K] fp32
__global__ void splitA3(const float* __restrict__ src, __nv_bfloat16* __restrict__ dst,
                        int n, int K) {
    int i = blockIdx.x * blockDim.x + threadIdx.x;
    if (i >= n) return;
    int r = i / K, k = i % K;
    __nv_bfloat16 hi, lo; split2(src[i], hi, lo);
    size_t base = (size_t)r * 3 * K;
    dst[base + k] = hi; dst[base + K + k] = lo; dst[base + 2 * K + k] = hi;
}

// B-style split: dst row = [hi | hi | lo]
__global__ void splitB3(const float* __restrict__ src, __nv_bfloat16* __restrict__ dst,
                        int n, int K) {
    int i = blockIdx.x * blockDim.x + threadIdx.x;
    if (i >= n) return;
    int r = i / K, k = i % K;
    __nv_bfloat16 hi, lo; split2(src[i], hi, lo);
    size_t base = (size_t)r * 3 * K;
    dst[base + k] = hi; dst[base + K + k] = hi; dst[base + 2 * K + k] = lo;
}

__global__ void build_wcat3(const float* __restrict__ Wa, const float* __restrict__ Whh,
                            const float* __restrict__ ba, const float* __restrict__ bhh) {
    int i = blockIdx.x * blockDim.x + threadIdx.x;   // 4096*1024
    int r = i >> 10, k = i & (H_ - 1);
    float v = (r < H_) ? Wa[i] : Whh[i - H_ * H_];
    __nv_bfloat16 hi, lo; split2(v, hi, lo);
    size_t base = (size_t)r * K3_;
    g_Wcat3[base + k] = hi; g_Wcat3[base + H_ + k] = hi; g_Wcat3[base + 2 * H_ + k] = lo;
    if (i < 4 * H_) g_biascat[i] = (i < H_) ? ba[i] : bhh[i - H_];
}

__global__ void split_wih3(const float* __restrict__ W_ih) {
    int i = blockIdx.x * blockDim.x + threadIdx.x;   // 3072*2048
    int r = i >> 11, c = i & (2 * H_ - 1);
    __nv_bfloat16 hi, lo; split2(W_ih[i], hi, lo);
    if (c < H_) {
        size_t base = (size_t)r * K3_;
        g_Wihx3[base + c] = hi; g_Wihx3[base + H_ + c] = hi; g_Wihx3[base + 2 * H_ + c] = lo;
    } else {
        int c2 = c - H_;
        size_t base = (size_t)r * K3_;
        g_Wihc3[base + c2] = hi; g_Wihc3[base + H_ + c2] = hi; g_Wihc3[base + 2 * H_ + c2] = lo;
    }
}

__global__ void gather_emb3(const int* __restrict__ target, const float* __restrict__ embedding) {
    int i = blockIdx.x * blockDim.x + threadIdx.x;   // 2560*1024
    int row = i >> 10, hh = i & (H_ - 1);
    int b = row / T_, t = row % T_;
    int tok = (t == 0) ? 0 : target[b * T_ + t - 1];
    __nv_bfloat16 hi, lo; split2(embedding[(size_t)tok * H_ + hh], hi, lo);
    size_t base = (size_t)row * K3_;
    g_emb3[base + hh] = hi; g_emb3[base + H_ + hh] = lo; g_emb3[base + 2 * H_ + hh] = hi;
}

__global__ void init_h(const float* __restrict__ eh) {
    int i = blockIdx.x * blockDim.x + threadIdx.x;   // 65536
    int b = i >> 10, hh = i & (H_ - 1);
    float v = eh[i];
    g_h[i] = v;
    __nv_bfloat16 hi, lo; split2(v, hi, lo);
    size_t base = (size_t)b * K3_;
    g_h3[base + hh] = hi; g_h3[base + H_ + hh] = lo; g_h3[base + 2 * H_ + hh] = hi;
}

// ----------------------------- attention + gi_c -------------------------------
__global__ __launch_bounds__(256)
void attn_kernel(const float* __restrict__ Va, const float* __restrict__ bv,
                 float* __restrict__ out_attn, int t)
{
    __shared__ float s_q[H_];
    __shared__ float s_va[H_];
    __shared__ float s_sc[S_];
    const int b = blockIdx.x;
    const int tid = threadIdx.x;
    const int warp = tid >> 5, lane = tid & 31;

    for (int i = tid; i < H_; i += 256) {
        s_q[i]  = g_qgh[b * 4 * H_ + i];
        s_va[i] = Va[i];
    }
    __syncthreads();

    // scores[s] = Va . tanh(q + keysU[b,s,:]) + bv
    for (int s = warp; s < S_; s += 8) {
        const float* kr = g_keysU + ((size_t)b * S_ + s) * H_;
        float a = 0.f;
        for (int h = lane; h < H_; h += 32)
            a += s_va[h] * fast_tanh(s_q[h] + kr[h]);
        #pragma unroll
        for (int o = 16; o; o >>= 1) a += __shfl_xor_sync(0xffffffffu, a, o);
        if (lane == 0) s_sc[s] = a + bv[0];
    }
    __syncthreads();

    // softmax over S=64 in warp 0
    if (warp == 0) {
        float v0 = s_sc[lane], v1 = s_sc[lane + 32];
        float m = fmaxf(v0, v1);
        #pragma unroll
        for (int o = 16; o; o >>= 1) m = fmaxf(m, __shfl_xor_sync(0xffffffffu, m, o));
        float e0 = __expf(v0 - m), e1 = __expf(v1 - m);
        float ss = e0 + e1;
        #pragma unroll
        for (int o = 16; o; o >>= 1) ss += __shfl_xor_sync(0xffffffffu, ss, o);
        float inv = 1.f / ss;
        s_sc[lane] = e0 * inv;
        s_sc[lane + 32] = e1 * inv;
    }
    __syncthreads();

    if (tid < S_) out_attn[((size_t)b * T_ + t) * S_ + tid] = s_sc[tid];

    // gi_c[b,:] = sum_s w[s] * encWc[b,s,:]   (fully fp32)
    for (int h = tid; h < 3 * H_; h += 256) {
        const float* er = g_encWc + (size_t)b * S_ * 3 * H_ + h;
        float a = 0.f;
        #pragma unroll 8
        for (int s = 0; s < S_; s++) a += s_sc[s] * er[(size_t)s * 3 * H_];
        g_gic[b * 3 * H_ + h] = a;
    }
}

// ----------------------------- GRU update ------------------------------------
__global__ __launch_bounds__(256)
void gru_update(float* __restrict__ out_hidden, int t)
{
    int i = blockIdx.x * blockDim.x + threadIdx.x;   // 65536
    int b = i >> 10, hh = i & (H_ - 1);
    const float* gi = g_gix + (size_t)(b * T_ + t) * 3 * H_;
    const float* gc = g_gic + b * 3 * H_;
    const float* gh = g_qgh + b * 4 * H_ + H_;

    float ir  = gi[hh]          + gc[hh];
    float iz  = gi[H_ + hh]     + gc[H_ + hh];
    float in_ = gi[2 * H_ + hh] + gc[2 * H_ + hh];
    float hr = gh[hh], hz = gh[H_ + hh], hn = gh[2 * H_ + hh];

    float r = 1.f / (1.f + expf(-(ir + hr)));
    float z = 1.f / (1.f + expf(-(iz + hz)));
    float n = tanhf(in_ + r * hn);
    float hprev = g_h[i];
    float hnew = (1.f - z) * n + z * hprev;

    g_h[i] = hnew;
    __nv_bfloat16 hi, lo; split2(hnew, hi, lo);
    size_t base = (size_t)b * K3_;
    g_h3[base + hh] = hi; g_h3[base + H_ + hh] = lo; g_h3[base + 2 * H_ + hh] = hi;
    g_Hall_b[(size_t)(b * T_ + t) * H_ + hh] = __float2bfloat16(hnew);
    if (t == T_ - 1) out_hidden[i] = hnew;
}

// ----------------------------- log-softmax (in place) ------------------------
__global__ __launch_bounds__(256)
void logsoftmax_kernel(float* __restrict__ x)
{
    __shared__ float red[32];
    float* p = x + (size_t)blockIdx.x * V_;
    const int tid = threadIdx.x;

    float m = -1e30f;
    for (int i = tid; i < V_; i += 256) m = fmaxf(m, p[i]);
    #pragma unroll
    for (int o = 16; o; o >>= 1) m = fmaxf(m, __shfl_xor_sync(0xffffffffu, m, o));
    if ((tid & 31) == 0) red[tid >> 5] = m;
    __syncthreads();
    if (tid < 32) {
        float v = (tid < 8) ? red[tid] : -1e30f;
        #pragma unroll
        for (int o = 16; o; o >>= 1) v = fmaxf(v, __shfl_xor_sync(0xffffffffu, v, o));
        red[tid] = v;
    }
    __syncthreads();
    m = red[0];
    __syncthreads();

    float s = 0.f;
    for (int i = tid; i < V_; i += 256) s += __expf(p[i] - m);
    #pragma unroll
    for (int o = 16; o; o >>= 1) s += __shfl_xor_sync(0xffffffffu, s, o);
    if ((tid & 31) == 0) red[tid >> 5] = s;
    __syncthreads();
    if (tid == 0) {
        float tot = 0.f;
        #pragma unroll
        for (int w = 0; w < 8; w++) tot += red[w];
        red[0] = m + logf(tot);
    }
    __syncthreads();
    float lse = red[0];
    for (int i = tid; i < V_; i += 256) p[i] -= lse;
}

// ----------------------------- host launcher ----------------------------------
template <typename Tp>
static Tp* sym_addr(const void* sym) {
    void* p = nullptr;
    cudaGetSymbolAddress(&p, sym);
    return (Tp*)p;
}

// GEMM configs
#define BIG_CFG  128, 128, 32, 32, 64, 4
#define SML_CFG  64, 64, 64, 32, 32, 3
static constexpr int SMEM_BIG = 4 * (128 + 128) * (32 + 8) * 2;  // 81920
static constexpr int SMEM_SML = 3 * (64 + 64) * (64 + 8) * 2;    // 55296

extern "C" void kernel_launch(void* const* d_in, const int* in_sizes, int n_in,
                              void* d_out, int out_size)
{
    const float* enc       = (const float*)d_in[0];
    const float* ehid      = (const float*)d_in[1];
    const int*   target    = (const int*)d_in[2];
    const float* embedding = (const float*)d_in[3];
    const float* Wa        = (const float*)d_in[4];
    const float* ba        = (const float*)d_in[5];
    const float* Ua        = (const float*)d_in[6];
    const float* bu        = (const float*)d_in[7];
    const float* Va        = (const float*)d_in[8];
    const float* bv        = (const float*)d_in[9];
    const float* W_ih      = (const float*)d_in[10];
    const float* W_hh      = (const float*)d_in[11];
    const float* b_ih      = (const float*)d_in[12];
    const float* b_hh      = (const float*)d_in[13];
    const float* W_out     = (const float*)d_in[14];
    const float* b_out     = (const float*)d_in[15];

    float* out      = (float*)d_out;
    float* out_dec  = out;                                    // [B,T,V]
    float* out_hid  = out + (size_t)B_ * T_ * V_;             // [1,B,H]
    float* out_attn = out_hid + (size_t)B_ * H_;              // [B,T,S]

    __nv_bfloat16* p_Wout  = sym_addr<__nv_bfloat16>(g_Wout_b);
    __nv_bfloat16* p_Wcat3 = sym_addr<__nv_bfloat16>(g_Wcat3);
    __nv_bfloat16* p_Wihx3 = sym_addr<__nv_bfloat16>(g_Wihx3);
    __nv_bfloat16* p_Wihc3 = sym_addr<__nv_bfloat16>(g_Wihc3);
    __nv_bfloat16* p_Ua3   = sym_addr<__nv_bfloat16>(g_Ua3);
    __nv_bfloat16* p_enc3  = sym_addr<__nv_bfloat16>(g_enc3);
    __nv_bfloat16* p_emb3  = sym_addr<__nv_bfloat16>(g_emb3);
    __nv_bfloat16* p_h3    = sym_addr<__nv_bfloat16>(g_h3);
    __nv_bfloat16* p_Hall  = sym_addr<__nv_bfloat16>(g_Hall_b);
    float* p_keysU = sym_addr<float>(g_keysU);
    float* p_encWc = sym_addr<float>(g_encWc);
    float* p_gix   = sym_addr<float>(g_gix);
    float* p_qgh   = sym_addr<float>(g_qgh);
    float* p_bcat  = sym_addr<float>(g_biascat);

    cudaFuncSetAttribute(gemm_tn_pipe<BIG_CFG>,
                         cudaFuncAttributeMaxDynamicSharedMemorySize, SMEM_BIG);
    cudaFuncSetAttribute(gemm_tn_pipe<SML_CFG>,
                         cudaFuncAttributeMaxDynamicSharedMemorySize, SMEM_SML);

    // ---- conversions / splits ----
    conv_f2b<<<(V_ * H_) / 256, 256>>>(W_out, p_Wout, V_ * H_);
    splitA3<<<(B_ * S_ * H_) / 256, 256>>>(enc, p_enc3, B_ * S_ * H_, H_);
    splitB3<<<(H_ * H_) / 256, 256>>>(Ua, p_Ua3, H_ * H_, H_);
    build_wcat3<<<(4 * H_ * H_) / 256, 256>>>(Wa, W_hh, ba, b_hh);
    split_wih3<<<(3 * H_ * 2 * H_) / 256, 256>>>(W_ih);
    gather_emb3<<<(B_ * T_ * H_) / 256, 256>>>(target, embedding);
    init_h<<<(B_ * H_) / 256, 256>>>(ehid);

    // keysU = enc @ Ua^T + bu : [4096, 1024], split K=3072
    {
        dim3 grid(H_ / 128, (B_ * S_) / 128);
        gemm_tn_pipe<BIG_CFG><<<grid, 256, SMEM_BIG>>>(
            p_enc3, K3_, p_Ua3, K3_, bu, p_keysU, H_, B_ * S_, H_, K3_);
    }
    // gi_x = emb @ W_ihx^T + b_ih : [2560, 3072], split K=3072
    {
        dim3 grid((3 * H_) / 128, (B_ * T_) / 128);
        gemm_tn_pipe<BIG_CFG><<<grid, 256, SMEM_BIG>>>(
            p_emb3, K3_, p_Wihx3, K3_, b_ih, p_gix, 3 * H_, B_ * T_, 3 * H_, K3_);
    }
    // encWc = enc @ W_ihc^T : [4096, 3072], split K=3072
    {
        dim3 grid((3 * H_) / 128, (B_ * S_) / 128);
        gemm_tn_pipe<BIG_CFG><<<grid, 256, SMEM_BIG>>>(
            p_enc3, K3_, p_Wihc3, K3_, nullptr, p_encWc, 3 * H_, B_ * S_, 3 * H_, K3_);
    }

    // ---- recurrence ----
    for (int t = 0; t < T_; t++) {
        // [q | gh] = h @ [Wa;W_hh]^T + [ba;b_hh] : [64, 4096], split K=3072
        {
            dim3 grid((4 * H_) / 64, 1);
            gemm_tn_pipe<SML_CFG><<<grid, 128, SMEM_SML>>>(
                p_h3, K3_, p_Wcat3, K3_, p_bcat, p_qgh, 4 * H_, B_, 4 * H_, K3_);
        }
        attn_kernel<<<B_, 256>>>(Va, bv, out_attn, t);
        gru_update<<<(B_ * H_) / 256, 256>>>(out_hid, t);
    }

    // ---- output projection: logits = Hall @ W_out^T + b_out (plain bf16, K=1024)
    {
        dim3 grid(V_ / 128, (B_ * T_) / 128);
        gemm_tn_pipe<BIG_CFG><<<grid, 256, SMEM_BIG>>>(
            p_Hall, H_, p_Wout, H_, b_out, out_dec, V_, B_ * T_, V_, H_);
    }
    logsoftmax_kernel<<<B_ * T_, 256>>>(out_dec);
}

// round 5
// speedup vs baseline: 1.7512x; 1.7512x over previous
#include <cuda_runtime.h>
#include <cuda_bf16.h>
#include <cstdint>

// Problem dims
#define B_  64
#define S_  64
#define H_  1024
#define V_  32000
#define T_  40
#define K3_ (3 * H_)   // split-K width
#define NZ_ 6          // z-split factor for recurrent GEMM
#define KW_ (K3_ / NZ_) // 512
#define B4H_ (B_ * 4 * H_)

#define DINLINE __device__ __forceinline__

// ----------------------------- scratch (static device memory) ----------------
__device__ __nv_bfloat16 g_Wout_b[(size_t)V_ * H_];          // 64 MB (plain bf16)
__device__ __nv_bfloat16 g_Wcat3[(size_t)4 * H_ * K3_];      // [Wa;W_hh] B-split
__device__ __nv_bfloat16 g_Wihx3[(size_t)3 * H_ * K3_];      // W_ih[:, :H] B-split
__device__ __nv_bfloat16 g_Wihc3[(size_t)3 * H_ * K3_];      // W_ih[:, H:] B-split
__device__ __nv_bfloat16 g_Ua3[(size_t)H_ * K3_];            // B-split
__device__ __nv_bfloat16 g_enc3[(size_t)B_ * S_ * K3_];      // A-split
__device__ __nv_bfloat16 g_emb3[(size_t)B_ * T_ * K3_];      // A-split
__device__ __nv_bfloat16 g_h3[B_ * K3_];                     // A-split of h
__device__ float         g_keysU[(size_t)B_ * S_ * H_];
__device__ float         g_encWc[(size_t)B_ * S_ * 3 * H_];  // 50 MB
__device__ float         g_gix[(size_t)B_ * T_ * 3 * H_];
__device__ float         g_qgh6[(size_t)NZ_ * B4H_];         // 6 K-partials of [q|gh]
__device__ float         g_h[B_ * H_];
__device__ __nv_bfloat16 g_Hall_b[B_ * T_ * H_];
__device__ float         g_biascat[4 * H_];

// ----------------------------- helpers ---------------------------------------
DINLINE uint32_t smem_u32(const void* p) {
    return (uint32_t)__cvta_generic_to_shared(p);
}
DINLINE void cp_async16(void* sp, const void* gp) {
    asm volatile("cp.async.cg.shared.global [%0], [%1], 16;"
                 :: "r"(smem_u32(sp)), "l"(gp));
}
DINLINE void cp_commit() { asm volatile("cp.async.commit_group;"); }
template <int N> DINLINE void cp_wait() {
    asm volatile("cp.async.wait_group %0;" :: "n"(N));
}
DINLINE void ldmx4(uint32_t& r0, uint32_t& r1, uint32_t& r2, uint32_t& r3, uint32_t a) {
    asm volatile("ldmatrix.sync.aligned.m8n8.x4.shared.b16 {%0,%1,%2,%3}, [%4];"
                 : "=r"(r0), "=r"(r1), "=r"(r2), "=r"(r3) : "r"(a));
}
DINLINE void ldmx2(uint32_t& r0, uint32_t& r1, uint32_t a) {
    asm volatile("ldmatrix.sync.aligned.m8n8.x2.shared.b16 {%0,%1}, [%2];"
                 : "=r"(r0), "=r"(r1) : "r"(a));
}
DINLINE void mma_bf16(float& c0, float& c1, float& c2, float& c3,
                      uint32_t a0, uint32_t a1, uint32_t a2, uint32_t a3,
                      uint32_t b0, uint32_t b1) {
    asm volatile("mma.sync.aligned.m16n8k16.row.col.f32.bf16.bf16.f32 "
                 "{%0,%1,%2,%3}, {%4,%5,%6,%7}, {%8,%9}, {%0,%1,%2,%3};"
                 : "+f"(c0), "+f"(c1), "+f"(c2), "+f"(c3)
                 : "r"(a0), "r"(a1), "r"(a2), "r"(a3), "r"(b0), "r"(b1));
}
DINLINE float fast_tanh(float x) {
    float y; asm("tanh.approx.f32 %0, %1;" : "=f"(y) : "f"(x)); return y;
}
DINLINE void split2(float x, __nv_bfloat16& hi, __nv_bfloat16& lo) {
    hi = __float2bfloat16(x);
    lo = __float2bfloat16(x - __bfloat162float(hi));
}

// ----------------------------- pipelined TN bf16 GEMM --------------------------
// C[M,N](f32) = A[M,K](bf16,lda) @ B[N,K](bf16,ldb)^T + bias[N]
// blockIdx.z splits K: A/B shifted by z*kOff elements, C by z*cOff; bias z==0 only.
template <int BM, int BN, int BK, int WM, int WN, int STAGES>
__global__ __launch_bounds__((BM / WM) * (BN / WN) * 32)
void gemm_tn_pipe(const __nv_bfloat16* __restrict__ A, int lda,
                  const __nv_bfloat16* __restrict__ Bm, int ldb,
                  const float* __restrict__ bias,
                  float* __restrict__ C, int ldc,
                  int M, int N, int K, int kOff, size_t cOff)
{
    constexpr int WARPS_M = BM / WM;
    constexpr int WARPS_N = BN / WN;
    constexpr int NT = WARPS_M * WARPS_N * 32;
    constexpr int PAD = 8;
    constexpr int LDSM = BK + PAD;
    constexpr int MFRAG = WM / 16;
    constexpr int NFRAG = WN / 8;
    constexpr int AV = BM * BK / 8;
    constexpr int BV = BN * BK / 8;

    const int bz = blockIdx.z;
    A  += (size_t)bz * kOff;
    Bm += (size_t)bz * kOff;
    C  += (size_t)bz * cOff;
    if (bz) bias = nullptr;

    extern __shared__ __nv_bfloat16 smem[];
    __nv_bfloat16* As = smem;
    __nv_bfloat16* Bs = smem + (size_t)STAGES * BM * LDSM;

    const int bm = blockIdx.y * BM;
    const int bn = blockIdx.x * BN;
    const int tid = threadIdx.x;
    const int warp = tid >> 5, lane = tid & 31;
    const int wm = (warp % WARPS_M) * WM;
    const int wn = (warp / WARPS_M) * WN;
    const int KT = K / BK;

    auto issue = [&](int slot, int kt) {
        const __nv_bfloat16* Ab = A + (size_t)bm * lda + kt * BK;
        const __nv_bfloat16* Bb = Bm + (size_t)bn * ldb + kt * BK;
        __nv_bfloat16* As_s = As + (size_t)slot * BM * LDSM;
        __nv_bfloat16* Bs_s = Bs + (size_t)slot * BN * LDSM;
        #pragma unroll
        for (int v = tid; v < AV; v += NT) {
            int r = v / (BK / 8), c = (v % (BK / 8)) * 8;
            cp_async16(&As_s[r * LDSM + c], Ab + (size_t)r * lda + c);
        }
        #pragma unroll
        for (int v = tid; v < BV; v += NT) {
            int r = v / (BK / 8), c = (v % (BK / 8)) * 8;
            cp_async16(&Bs_s[r * LDSM + c], Bb + (size_t)r * ldb + c);
        }
    };

    #pragma unroll
    for (int s = 0; s < STAGES - 1; s++) {
        if (s < KT) issue(s, s);
        cp_commit();
    }

    float acc[MFRAG][NFRAG][4] = {};

    for (int kt = 0; kt < KT; kt++) {
        cp_wait<STAGES - 2>();
        __syncthreads();
        int nxt = kt + STAGES - 1;
        if (nxt < KT) issue(nxt % STAGES, nxt);
        cp_commit();

        const __nv_bfloat16* As_s = As + (size_t)(kt % STAGES) * BM * LDSM;
        const __nv_bfloat16* Bs_s = Bs + (size_t)(kt % STAGES) * BN * LDSM;

        #pragma unroll
        for (int kk = 0; kk < BK; kk += 16) {
            uint32_t af[MFRAG][4];
            #pragma unroll
            for (int mi = 0; mi < MFRAG; mi++) {
                int row = wm + mi * 16 + (lane & 15);
                int col = kk + (lane >> 4) * 8;
                ldmx4(af[mi][0], af[mi][1], af[mi][2], af[mi][3],
                      smem_u32(&As_s[row * LDSM + col]));
            }
            uint32_t bfr[NFRAG][2];
            #pragma unroll
            for (int ni = 0; ni < NFRAG; ni++) {
                int row = wn + ni * 8 + (lane & 7);
                int col = kk + ((lane >> 3) & 1) * 8;
                ldmx2(bfr[ni][0], bfr[ni][1], smem_u32(&Bs_s[row * LDSM + col]));
            }
            #pragma unroll
            for (int mi = 0; mi < MFRAG; mi++)
                #pragma unroll
                for (int ni = 0; ni < NFRAG; ni++)
                    mma_bf16(acc[mi][ni][0], acc[mi][ni][1], acc[mi][ni][2], acc[mi][ni][3],
                             af[mi][0], af[mi][1], af[mi][2], af[mi][3],
                             bfr[ni][0], bfr[ni][1]);
        }
        __syncthreads();
    }

    #pragma unroll
    for (int mi = 0; mi < MFRAG; mi++) {
        #pragma unroll
        for (int ni = 0; ni < NFRAG; ni++) {
            int r0 = bm + wm + mi * 16 + (lane >> 2);
            int c0 = bn + wn + ni * 8 + (lane & 3) * 2;
            float b0 = bias ? bias[c0] : 0.f;
            float b1 = bias ? bias[c0 + 1] : 0.f;
            if (r0 < M) {
                C[(size_t)r0 * ldc + c0]     = acc[mi][ni][0] + b0;
                C[(size_t)r0 * ldc + c0 + 1] = acc[mi][ni][1] + b1;
            }
            if (r0 + 8 < M) {
                C[(size_t)(r0 + 8) * ldc + c0]     = acc[mi][ni][2] + b0;
                C[(size_t)(r0 + 8) * ldc + c0 + 1] = acc[mi][ni][3] + b1;
            }
        }
    }
}

// ----------------------------- prep kernels ----------------------------------
// vectorized f32 -> bf16 (4 elems/thread)
__global__ void conv_f2b_v4(const float* __restrict__ s, __nv_bfloat16* __restrict__ d, int n4) {
    int i = blockIdx.x * blockDim.x + threadIdx.x;
    if (i >= n4) return;
    float4 v = ((const float4*)s)[i];
    __nv_bfloat162 p0(__float2bfloat16(v.x), __float2bfloat16(v.y));
    __nv_bfloat162 p1(__float2bfloat16(v.z), __float2bfloat16(v.w));
    ((__nv_bfloat162*)d)[i * 2]     = p0;
    ((__nv_bfloat162*)d)[i * 2 + 1] = p1;
}

__global__ void splitA3(const float* __restrict__ src, __nv_bfloat16* __restrict__ dst,
                        int n, int K) {
    int i = blockIdx.x * blockDim.x + threadIdx.x;
    if (i >= n) return;
    int r = i / K, k = i % K;
    __nv_bfloat16 hi, lo; split2(src[i], hi, lo);
    size_t base = (size_t)r * 3 * K;
    dst[base + k] = hi; dst[base + K + k] = lo; dst[base + 2 * K + k] = hi;
}

__global__ void splitB3(const float* __restrict__ src, __nv_bfloat16* __restrict__ dst,
                        int n, int K) {
    int i = blockIdx.x * blockDim.x + threadIdx.x;
    if (i >= n) return;
    int r = i / K, k = i % K;
    __nv_bfloat16 hi, lo; split2(src[i], hi, lo);
    size_t base = (size_t)r * 3 * K;
    dst[base + k] = hi; dst[base + K + k] = hi; dst[base + 2 * K + k] = lo;
}

__global__ void build_wcat3(const float* __restrict__ Wa, const float* __restrict__ Whh,
                            const float* __restrict__ ba, const float* __restrict__ bhh) {
    int i = blockIdx.x * blockDim.x + threadIdx.x;   // 4096*1024
    int r = i >> 10, k = i & (H_ - 1);
    float v = (r < H_) ? Wa[i] : Whh[i - H_ * H_];
    __nv_bfloat16 hi, lo; split2(v, hi, lo);
    size_t base = (size_t)r * K3_;
    g_Wcat3[base + k] = hi; g_Wcat3[base + H_ + k] = hi; g_Wcat3[base + 2 * H_ + k] = lo;
    if (i < 4 * H_) g_biascat[i] = (i < H_) ? ba[i] : bhh[i - H_];
}

__global__ void split_wih3(const float* __restrict__ W_ih) {
    int i = blockIdx.x * blockDim.x + threadIdx.x;   // 3072*2048
    int r = i >> 11, c = i & (2 * H_ - 1);
    __nv_bfloat16 hi, lo; split2(W_ih[i], hi, lo);
    if (c < H_) {
        size_t base = (size_t)r * K3_;
        g_Wihx3[base + c] = hi; g_Wihx3[base + H_ + c] = hi; g_Wihx3[base + 2 * H_ + c] = lo;
    } else {
        int c2 = c - H_;
        size_t base = (size_t)r * K3_;
        g_Wihc3[base + c2] = hi; g_Wihc3[base + H_ + c2] = hi; g_Wihc3[base + 2 * H_ + c2] = lo;
    }
}

__global__ void gather_emb3(const int* __restrict__ target, const float* __restrict__ embedding) {
    int i = blockIdx.x * blockDim.x + threadIdx.x;   // 2560*1024
    int row = i >> 10, hh = i & (H_ - 1);
    int b = row / T_, t = row % T_;
    int tok = (t == 0) ? 0 : target[b * T_ + t - 1];
    __nv_bfloat16 hi, lo; split2(embedding[(size_t)tok * H_ + hh], hi, lo);
    size_t base = (size_t)row * K3_;
    g_emb3[base + hh] = hi; g_emb3[base + H_ + hh] = lo; g_emb3[base + 2 * H_ + hh] = hi;
}

__global__ void init_h(const float* __restrict__ eh) {
    int i = blockIdx.x * blockDim.x + threadIdx.x;   // 65536
    int b = i >> 10, hh = i & (H_ - 1);
    float v = eh[i];
    g_h[i] = v;
    __nv_bfloat16 hi, lo; split2(v, hi, lo);
    size_t base = (size_t)b * K3_;
    g_h3[base + hh] = hi; g_h3[base + H_ + hh] = lo; g_h3[base + 2 * H_ + hh] = hi;
}

// ----------------------------- fused attention + GRU --------------------------
__global__ __launch_bounds__(256)
void attn_gru(const float* __restrict__ Va, const float* __restrict__ bv,
              float* __restrict__ out_attn, float* __restrict__ out_hidden, int t)
{
    __shared__ __align__(16) float s_q[H_];
    __shared__ __align__(16) float s_va[H_];
    __shared__ float s_sc[S_];
    const int b = blockIdx.x;
    const int tid = threadIdx.x;
    const int warp = tid >> 5, lane = tid & 31;

    // q = sum of 6 K-partials (bias ba folded into partial 0)
    for (int i = tid; i < H_; i += 256) {
        float a = 0.f;
        #pragma unroll
        for (int z = 0; z < NZ_; z++)
            a += g_qgh6[(size_t)z * B4H_ + b * 4 * H_ + i];
        s_q[i]  = a;
        s_va[i] = Va[i];
    }
    __syncthreads();

    // scores[s] = Va . tanh(q + keysU[b,s,:]) + bv     (float4 loads)
    for (int s = warp; s < S_; s += 8) {
        const float4* kr = (const float4*)(g_keysU + ((size_t)b * S_ + s) * H_);
        const float4* q4p = (const float4*)s_q;
        const float4* v4p = (const float4*)s_va;
        float a = 0.f;
        #pragma unroll 4
        for (int j = lane; j < H_ / 4; j += 32) {
            float4 k4 = kr[j];
            float4 q4 = q4p[j];
            float4 v4 = v4p[j];
            a += v4.x * fast_tanh(q4.x + k4.x) + v4.y * fast_tanh(q4.y + k4.y)
               + v4.z * fast_tanh(q4.z + k4.z) + v4.w * fast_tanh(q4.w + k4.w);
        }
        #pragma unroll
        for (int o = 16; o; o >>= 1) a += __shfl_xor_sync(0xffffffffu, a, o);
        if (lane == 0) s_sc[s] = a + bv[0];
    }
    __syncthreads();

    // softmax over S=64 in warp 0
    if (warp == 0) {
        float v0 = s_sc[lane], v1 = s_sc[lane + 32];
        float m = fmaxf(v0, v1);
        #pragma unroll
        for (int o = 16; o; o >>= 1) m = fmaxf(m, __shfl_xor_sync(0xffffffffu, m, o));
        float e0 = __expf(v0 - m), e1 = __expf(v1 - m);
        float ss = e0 + e1;
        #pragma unroll
        for (int o = 16; o; o >>= 1) ss += __shfl_xor_sync(0xffffffffu, ss, o);
        float inv = 1.f / ss;
        s_sc[lane] = e0 * inv;
        s_sc[lane + 32] = e1 * inv;
    }
    __syncthreads();

    if (tid < S_) out_attn[((size_t)b * T_ + t) * S_ + tid] = s_sc[tid];

    // ---- fused gi_c contraction + GRU gates, 4 consecutive h per thread ----
    const int hh = tid * 4;
    float4 gcr = make_float4(0.f, 0.f, 0.f, 0.f);
    float4 gcz = make_float4(0.f, 0.f, 0.f, 0.f);
    float4 gcn = make_float4(0.f, 0.f, 0.f, 0.f);
    const float* base = g_encWc + (size_t)b * S_ * 3 * H_;
    #pragma unroll 4
    for (int s = 0; s < S_; s++) {
        float w = s_sc[s];
        const float* row = base + (size_t)s * 3 * H_;
        float4 r4 = *(const float4*)(row + hh);
        float4 z4 = *(const float4*)(row + H_ + hh);
        float4 n4 = *(const float4*)(row + 2 * H_ + hh);
        gcr.x += w * r4.x; gcr.y += w * r4.y; gcr.z += w * r4.z; gcr.w += w * r4.w;
        gcz.x += w * z4.x; gcz.y += w * z4.y; gcz.z += w * z4.z; gcz.w += w * z4.w;
        gcn.x += w * n4.x; gcn.y += w * n4.y; gcn.z += w * n4.z; gcn.w += w * n4.w;
    }

    // gh parts (sum over 6 K-partials), bias b_hh folded into partial 0
    float4 ghr = make_float4(0.f, 0.f, 0.f, 0.f);
    float4 ghz = make_float4(0.f, 0.f, 0.f, 0.f);
    float4 ghn = make_float4(0.f, 0.f, 0.f, 0.f);
    #pragma unroll
    for (int z = 0; z < NZ_; z++) {
        const float* gp = g_qgh6 + (size_t)z * B4H_ + b * 4 * H_ + H_;
        float4 a = *(const float4*)(gp + hh);
        float4 c = *(const float4*)(gp + H_ + hh);
        float4 d = *(const float4*)(gp + 2 * H_ + hh);
        ghr.x += a.x; ghr.y += a.y; ghr.z += a.z; ghr.w += a.w;
        ghz.x += c.x; ghz.y += c.y; ghz.z += c.z; ghz.w += c.w;
        ghn.x += d.x; ghn.y += d.y; ghn.z += d.z; ghn.w += d.w;
    }

    const float* gi = g_gix + (size_t)(b * T_ + t) * 3 * H_;
    float4 gir = *(const float4*)(gi + hh);
    float4 giz = *(const float4*)(gi + H_ + hh);
    float4 gin = *(const float4*)(gi + 2 * H_ + hh);
    float4 hp  = *(const float4*)(g_h + b * H_ + hh);

    float hn4[4];
    #pragma unroll
    for (int q = 0; q < 4; q++) {
        float ir  = ((&gir.x)[q]) + ((&gcr.x)[q]);
        float iz  = ((&giz.x)[q]) + ((&gcz.x)[q]);
        float in_ = ((&gin.x)[q]) + ((&gcn.x)[q]);
        float hr = ((&ghr.x)[q]), hz = ((&ghz.x)[q]), hnn = ((&ghn.x)[q]);
        float r = 1.f / (1.f + expf(-(ir + hr)));
        float z = 1.f / (1.f + expf(-(iz + hz)));
        float n = tanhf(in_ + r * hnn);
        hn4[q] = (1.f - z) * n + z * ((&hp.x)[q]);
    }

    *(float4*)(g_h + b * H_ + hh) = make_float4(hn4[0], hn4[1], hn4[2], hn4[3]);

    __nv_bfloat16 hi[4], lo[4];
    #pragma unroll
    for (int q = 0; q < 4; q++) split2(hn4[q], hi[q], lo[q]);
    __nv_bfloat162 hi01(hi[0], hi[1]), hi23(hi[2], hi[3]);
    __nv_bfloat162 lo01(lo[0], lo[1]), lo23(lo[2], lo[3]);
    size_t b3 = (size_t)b * K3_;
    *(__nv_bfloat162*)&g_h3[b3 + hh]              = hi01;
    *(__nv_bfloat162*)&g_h3[b3 + hh + 2]          = hi23;
    *(__nv_bfloat162*)&g_h3[b3 + H_ + hh]         = lo01;
    *(__nv_bfloat162*)&g_h3[b3 + H_ + hh + 2]     = lo23;
    *(__nv_bfloat162*)&g_h3[b3 + 2 * H_ + hh]     = hi01;
    *(__nv_bfloat162*)&g_h3[b3 + 2 * H_ + hh + 2] = hi23;
    size_t hall = (size_t)(b * T_ + t) * H_ + hh;
    *(__nv_bfloat162*)&g_Hall_b[hall]     = hi01;
    *(__nv_bfloat162*)&g_Hall_b[hall + 2] = hi23;
    if (t == T_ - 1)
        *(float4*)(out_hidden + b * H_ + hh) = make_float4(hn4[0], hn4[1], hn4[2], hn4[3]);
}

// ----------------------------- online log-softmax (in place) ------------------
__global__ __launch_bounds__(512)
void logsoftmax_kernel(float* __restrict__ x)
{
    __shared__ float sm[16], ss[16];
    float* p = x + (size_t)blockIdx.x * V_;
    const int tid = threadIdx.x;

    // single online pass: running (max, sum)
    float m = -1e30f, sacc = 0.f;
    for (int i = tid; i < V_ / 4; i += 512) {
        float4 v = ((const float4*)p)[i];
        #pragma unroll
        for (int q = 0; q < 4; q++) {
            float xv = (&v.x)[q];
            if (xv > m) { sacc = sacc * __expf(m - xv) + 1.f; m = xv; }
            else        { sacc += __expf(xv - m); }
        }
    }
    #pragma unroll
    for (int o = 16; o; o >>= 1) {
        float m2 = __shfl_xor_sync(0xffffffffu, m, o);
        float s2 = __shfl_xor_sync(0xffffffffu, sacc, o);
        if (m2 > m) { sacc = sacc * __expf(m - m2) + s2; m = m2; }
        else        { sacc += s2 * __expf(m2 - m); }
    }
    if ((tid & 31) == 0) { sm[tid >> 5] = m; ss[tid >> 5] = sacc; }
    __syncthreads();
    if (tid == 0) {
        float M = sm[0], Sv = ss[0];
        #pragma unroll
        for (int w = 1; w < 16; w++) {
            float m2 = sm[w], s2 = ss[w];
            if (m2 > M) { Sv = Sv * __expf(M - m2) + s2; M = m2; }
            else        { Sv += s2 * __expf(m2 - M); }
        }
        sm[0] = M + logf(Sv);
    }
    __syncthreads();
    float lse = sm[0];
    for (int i = tid; i < V_ / 4; i += 512) {
        float4 v = ((const float4*)p)[i];
        v.x -= lse; v.y -= lse; v.z -= lse; v.w -= lse;
        ((float4*)p)[i] = v;
    }
}

// ----------------------------- host launcher ----------------------------------
template <typename Tp>
static Tp* sym_addr(const void* sym) {
    void* p = nullptr;
    cudaGetSymbolAddress(&p, sym);
    return (Tp*)p;
}

// GEMM configs
#define BIG_CFG  128, 128, 64, 64, 32, 3
#define SML_CFG  64, 64, 64, 32, 32, 3
static constexpr int SMEM_BIG = 3 * (128 + 128) * (64 + 8) * 2;  // 110592
static constexpr int SMEM_SML = 3 * (64 + 64) * (64 + 8) * 2;    // 55296

extern "C" void kernel_launch(void* const* d_in, const int* in_sizes, int n_in,
                              void* d_out, int out_size)
{
    const float* enc       = (const float*)d_in[0];
    const float* ehid      = (const float*)d_in[1];
    const int*   target    = (const int*)d_in[2];
    const float* embedding = (const float*)d_in[3];
    const float* Wa        = (const float*)d_in[4];
    const float* ba        = (const float*)d_in[5];
    const float* Ua        = (const float*)d_in[6];
    const float* bu        = (const float*)d_in[7];
    const float* Va        = (const float*)d_in[8];
    const float* bv        = (const float*)d_in[9];
    const float* W_ih      = (const float*)d_in[10];
    const float* W_hh      = (const float*)d_in[11];
    const float* b_ih      = (const float*)d_in[12];
    const float* b_hh      = (const float*)d_in[13];
    const float* W_out     = (const float*)d_in[14];
    const float* b_out     = (const float*)d_in[15];

    float* out      = (float*)d_out;
    float* out_dec  = out;                                    // [B,T,V]
    float* out_hid  = out + (size_t)B_ * T_ * V_;             // [1,B,H]
    float* out_attn = out_hid + (size_t)B_ * H_;              // [B,T,S]

    __nv_bfloat16* p_Wout  = sym_addr<__nv_bfloat16>(g_Wout_b);
    __nv_bfloat16* p_Wcat3 = sym_addr<__nv_bfloat16>(g_Wcat3);
    __nv_bfloat16* p_Wihx3 = sym_addr<__nv_bfloat16>(g_Wihx3);
    __nv_bfloat16* p_Wihc3 = sym_addr<__nv_bfloat16>(g_Wihc3);
    __nv_bfloat16* p_Ua3   = sym_addr<__nv_bfloat16>(g_Ua3);
    __nv_bfloat16* p_enc3  = sym_addr<__nv_bfloat16>(g_enc3);
    __nv_bfloat16* p_emb3  = sym_addr<__nv_bfloat16>(g_emb3);
    __nv_bfloat16* p_h3    = sym_addr<__nv_bfloat16>(g_h3);
    __nv_bfloat16* p_Hall  = sym_addr<__nv_bfloat16>(g_Hall_b);
    float* p_keysU = sym_addr<float>(g_keysU);
    float* p_encWc = sym_addr<float>(g_encWc);
    float* p_gix   = sym_addr<float>(g_gix);
    float* p_qgh6  = sym_addr<float>(g_qgh6);
    float* p_bcat  = sym_addr<float>(g_biascat);

    cudaFuncSetAttribute(gemm_tn_pipe<BIG_CFG>,
                         cudaFuncAttributeMaxDynamicSharedMemorySize, SMEM_BIG);
    cudaFuncSetAttribute(gemm_tn_pipe<SML_CFG>,
                         cudaFuncAttributeMaxDynamicSharedMemorySize, SMEM_SML);

    // ---- conversions / splits ----
    conv_f2b_v4<<<(V_ * H_ / 4 + 255) / 256, 256>>>(W_out, p_Wout, V_ * H_ / 4);
    splitA3<<<(B_ * S_ * H_) / 256, 256>>>(enc, p_enc3, B_ * S_ * H_, H_);
    splitB3<<<(H_ * H_) / 256, 256>>>(Ua, p_Ua3, H_ * H_, H_);
    build_wcat3<<<(4 * H_ * H_) / 256, 256>>>(Wa, W_hh, ba, b_hh);
    split_wih3<<<(3 * H_ * 2 * H_) / 256, 256>>>(W_ih);
    gather_emb3<<<(B_ * T_ * H_) / 256, 256>>>(target, embedding);
    init_h<<<(B_ * H_) / 256, 256>>>(ehid);

    // keysU = enc @ Ua^T + bu : [4096, 1024], split K=3072
    {
        dim3 grid(H_ / 128, (B_ * S_) / 128, 1);
        gemm_tn_pipe<BIG_CFG><<<grid, 256, SMEM_BIG>>>(
            p_enc3, K3_, p_Ua3, K3_, bu, p_keysU, H_, B_ * S_, H_, K3_, 0, 0);
    }
    // gi_x = emb @ W_ihx^T + b_ih : [2560, 3072], split K=3072
    {
        dim3 grid((3 * H_) / 128, (B_ * T_) / 128, 1);
        gemm_tn_pipe<BIG_CFG><<<grid, 256, SMEM_BIG>>>(
            p_emb3, K3_, p_Wihx3, K3_, b_ih, p_gix, 3 * H_, B_ * T_, 3 * H_, K3_, 0, 0);
    }
    // encWc = enc @ W_ihc^T : [4096, 3072], split K=3072
    {
        dim3 grid((3 * H_) / 128, (B_ * S_) / 128, 1);
        gemm_tn_pipe<BIG_CFG><<<grid, 256, SMEM_BIG>>>(
            p_enc3, K3_, p_Wihc3, K3_, nullptr, p_encWc, 3 * H_, B_ * S_, 3 * H_, K3_, 0, 0);
    }

    // ---- recurrence: 2 kernels per step ----
    for (int t = 0; t < T_; t++) {
        // qgh partials: [64, 4096] x 6 K-windows of 512
        {
            dim3 grid((4 * H_) / 64, 1, NZ_);
            gemm_tn_pipe<SML_CFG><<<grid, 128, SMEM_SML>>>(
                p_h3, K3_, p_Wcat3, K3_, p_bcat, p_qgh6, 4 * H_,
                B_, 4 * H_, KW_, KW_, (size_t)B4H_);
        }
        attn_gru<<<B_, 256>>>(Va, bv, out_attn, out_hid, t);
    }

    // ---- output projection: logits = Hall @ W_out^T + b_out (plain bf16, K=1024)
    {
        dim3 grid(V_ / 128, (B_ * T_) / 128, 1);
        gemm_tn_pipe<BIG_CFG><<<grid, 256, SMEM_BIG>>>(
            p_Hall, H_, p_Wout, H_, b_out, out_dec, V_, B_ * T_, V_, H_, 0, 0);
    }
    logsoftmax_kernel<<<B_ * T_, 512>>>(out_dec);
}

// round 8
// speedup vs baseline: 1.7577x; 1.0037x over previous
#include <cuda_runtime.h>
#include <cuda_bf16.h>
#include <cstdint>

// Problem dims
#define B_  64
#define S_  64
#define H_  1024
#define V_  32000
#define T_  40
#define K3_ (3 * H_)       // split-K width
#define B4H_ (B_ * 4 * H_)

// persistent recurrence kernel config
#define PGRID 128
#define PTHREADS 256
#define PBM 64
#define PBN 64
#define PBK 64
#define PSTG 3
#define PLDSM (PBK + 8)            // 72
#define PNZ 2
#define PKW (K3_ / PNZ)            // 1536
#define PKT (PKW / PBK)            // 24
#define PSMEM (PSTG * (PBM + PBN) * PLDSM * 2)   // 55296 bytes

#define DINLINE __device__ __forceinline__

// ----------------------------- scratch (static device memory) ----------------
__device__ __nv_bfloat16 g_Wout_b[(size_t)V_ * H_];          // 64 MB (plain bf16)
__device__ __nv_bfloat16 g_Wcat3[(size_t)4 * H_ * K3_];      // [Wa;W_hh] B-split
__device__ __nv_bfloat16 g_Wihx3[(size_t)3 * H_ * K3_];      // W_ih[:, :H] B-split
__device__ __nv_bfloat16 g_Wihc3[(size_t)3 * H_ * K3_];      // W_ih[:, H:] B-split
__device__ __nv_bfloat16 g_Ua3[(size_t)H_ * K3_];            // B-split
__device__ __nv_bfloat16 g_enc3[(size_t)B_ * S_ * K3_];      // A-split
__device__ __nv_bfloat16 g_emb3[(size_t)B_ * T_ * K3_];      // A-split
__device__ __nv_bfloat16 g_h3[B_ * K3_];                     // A-split of h
__device__ float         g_keysU[(size_t)B_ * S_ * H_];
__device__ float         g_encWc[(size_t)B_ * S_ * 3 * H_];  // 50 MB
__device__ float         g_gix[(size_t)B_ * T_ * 3 * H_];
__device__ float         g_qgh2[(size_t)PNZ * B4H_];         // 2 K-partials of [q|gh]
__device__ float         g_h[B_ * H_];
__device__ __nv_bfloat16 g_Hall_b[B_ * T_ * H_];
__device__ float         g_biascat[4 * H_];

// grid barrier state (self-resetting count; generation monotone across replays)
__device__ unsigned           g_bar_cnt = 0;
__device__ volatile unsigned  g_bar_gen = 0;

// ----------------------------- helpers ---------------------------------------
DINLINE uint32_t smem_u32(const void* p) {
    return (uint32_t)__cvta_generic_to_shared(p);
}
DINLINE void cp_async16(void* sp, const void* gp) {
    asm volatile("cp.async.cg.shared.global [%0], [%1], 16;"
                 :: "r"(smem_u32(sp)), "l"(gp));
}
DINLINE void cp_commit() { asm volatile("cp.async.commit_group;"); }
template <int N> DINLINE void cp_wait() {
    asm volatile("cp.async.wait_group %0;" :: "n"(N));
}
DINLINE void ldmx4(uint32_t& r0, uint32_t& r1, uint32_t& r2, uint32_t& r3, uint32_t a) {
    asm volatile("ldmatrix.sync.aligned.m8n8.x4.shared.b16 {%0,%1,%2,%3}, [%4];"
                 : "=r"(r0), "=r"(r1), "=r"(r2), "=r"(r3) : "r"(a));
}
DINLINE void ldmx2(uint32_t& r0, uint32_t& r1, uint32_t a) {
    asm volatile("ldmatrix.sync.aligned.m8n8.x2.shared.b16 {%0,%1}, [%2];"
                 : "=r"(r0), "=r"(r1) : "r"(a));
}
DINLINE void mma_bf16(float& c0, float& c1, float& c2, float& c3,
                      uint32_t a0, uint32_t a1, uint32_t a2, uint32_t a3,
                      uint32_t b0, uint32_t b1) {
    asm volatile("mma.sync.aligned.m16n8k16.row.col.f32.bf16.bf16.f32 "
                 "{%0,%1,%2,%3}, {%4,%5,%6,%7}, {%8,%9}, {%0,%1,%2,%3};"
                 : "+f"(c0), "+f"(c1), "+f"(c2), "+f"(c3)
                 : "r"(a0), "r"(a1), "r"(a2), "r"(a3), "r"(b0), "r"(b1));
}
DINLINE float fast_tanh(float x) {
    float y; asm("tanh.approx.f32 %0, %1;" : "=f"(y) : "f"(x)); return y;
}
DINLINE void split2(float x, __nv_bfloat16& hi, __nv_bfloat16& lo) {
    hi = __float2bfloat16(x);
    lo = __float2bfloat16(x - __bfloat162float(hi));
}

// ----------------------------- pipelined TN bf16 GEMM (big, standalone) -------
template <int BM, int BN, int BK, int WM, int WN, int STAGES>
__global__ __launch_bounds__((BM / WM) * (BN / WN) * 32)
void gemm_tn_pipe(const __nv_bfloat16* __restrict__ A, int lda,
                  const __nv_bfloat16* __restrict__ Bm, int ldb,
                  const float* __restrict__ bias,
                  float* __restrict__ C, int ldc,
                  int M, int N, int K)
{
    constexpr int WARPS_M = BM / WM;
    constexpr int WARPS_N = BN / WN;
    constexpr int NT = WARPS_M * WARPS_N * 32;
    constexpr int PAD = 8;
    constexpr int LDSM = BK + PAD;
    constexpr int MFRAG = WM / 16;
    constexpr int NFRAG = WN / 8;
    constexpr int AV = BM * BK / 8;
    constexpr int BV = BN * BK / 8;

    extern __shared__ __nv_bfloat16 smem[];
    __nv_bfloat16* As = smem;
    __nv_bfloat16* Bs = smem + (size_t)STAGES * BM * LDSM;

    const int bm = blockIdx.y * BM;
    const int bn = blockIdx.x * BN;
    const int tid = threadIdx.x;
    const int warp = tid >> 5, lane = tid & 31;
    const int wm = (warp % WARPS_M) * WM;
    const int wn = (warp / WARPS_M) * WN;
    const int KT = K / BK;

    auto issue = [&](int slot, int kt) {
        const __nv_bfloat16* Ab = A + (size_t)bm * lda + kt * BK;
        const __nv_bfloat16* Bb = Bm + (size_t)bn * ldb + kt * BK;
        __nv_bfloat16* As_s = As + (size_t)slot * BM * LDSM;
        __nv_bfloat16* Bs_s = Bs + (size_t)slot * BN * LDSM;
        #pragma unroll
        for (int v = tid; v < AV; v += NT) {
            int r = v / (BK / 8), c = (v % (BK / 8)) * 8;
            cp_async16(&As_s[r * LDSM + c], Ab + (size_t)r * lda + c);
        }
        #pragma unroll
        for (int v = tid; v < BV; v += NT) {
            int r = v / (BK / 8), c = (v % (BK / 8)) * 8;
            cp_async16(&Bs_s[r * LDSM + c], Bb + (size_t)r * ldb + c);
        }
    };

    #pragma unroll
    for (int s = 0; s < STAGES - 1; s++) {
        if (s < KT) issue(s, s);
        cp_commit();
    }

    float acc[MFRAG][NFRAG][4] = {};

    for (int kt = 0; kt < KT; kt++) {
        cp_wait<STAGES - 2>();
        __syncthreads();
        int nxt = kt + STAGES - 1;
        if (nxt < KT) issue(nxt % STAGES, nxt);
        cp_commit();

        const __nv_bfloat16* As_s = As + (size_t)(kt % STAGES) * BM * LDSM;
        const __nv_bfloat16* Bs_s = Bs + (size_t)(kt % STAGES) * BN * LDSM;

        #pragma unroll
        for (int kk = 0; kk < BK; kk += 16) {
            uint32_t af[MFRAG][4];
            #pragma unroll
            for (int mi = 0; mi < MFRAG; mi++) {
                int row = wm + mi * 16 + (lane & 15);
                int col = kk + (lane >> 4) * 8;
                ldmx4(af[mi][0], af[mi][1], af[mi][2], af[mi][3],
                      smem_u32(&As_s[row * LDSM + col]));
            }
            uint32_t bfr[NFRAG][2];
            #pragma unroll
            for (int ni = 0; ni < NFRAG; ni++) {
                int row = wn + ni * 8 + (lane & 7);
                int col = kk + ((lane >> 3) & 1) * 8;
                ldmx2(bfr[ni][0], bfr[ni][1], smem_u32(&Bs_s[row * LDSM + col]));
            }
            #pragma unroll
            for (int mi = 0; mi < MFRAG; mi++)
                #pragma unroll
                for (int ni = 0; ni < NFRAG; ni++)
                    mma_bf16(acc[mi][ni][0], acc[mi][ni][1], acc[mi][ni][2], acc[mi][ni][3],
                             af[mi][0], af[mi][1], af[mi][2], af[mi][3],
                             bfr[ni][0], bfr[ni][1]);
        }
        __syncthreads();
    }

    #pragma unroll
    for (int mi = 0; mi < MFRAG; mi++) {
        #pragma unroll
        for (int ni = 0; ni < NFRAG; ni++) {
            int r0 = bm + wm + mi * 16 + (lane >> 2);
            int c0 = bn + wn + ni * 8 + (lane & 3) * 2;
            float b0 = bias ? bias[c0] : 0.f;
            float b1 = bias ? bias[c0 + 1] : 0.f;
            if (r0 < M) {
                C[(size_t)r0 * ldc + c0]     = acc[mi][ni][0] + b0;
                C[(size_t)r0 * ldc + c0 + 1] = acc[mi][ni][1] + b1;
            }
            if (r0 + 8 < M) {
                C[(size_t)(r0 + 8) * ldc + c0]     = acc[mi][ni][2] + b0;
                C[(size_t)(r0 + 8) * ldc + c0 + 1] = acc[mi][ni][3] + b1;
            }
        }
    }
}

// ----------------------------- prep kernels ----------------------------------
__global__ void conv_f2b_v4(const float* __restrict__ s, __nv_bfloat16* __restrict__ d, int n4) {
    int i = blockIdx.x * blockDim.x + threadIdx.x;
    if (i >= n4) return;
    float4 v = ((const float4*)s)[i];
    __nv_bfloat162 p0(__float2bfloat16(v.x), __float2bfloat16(v.y));
    __nv_bfloat162 p1(__float2bfloat16(v.z), __float2bfloat16(v.w));
    ((__nv_bfloat162*)d)[i * 2]     = p0;
    ((__nv_bfloat162*)d)[i * 2 + 1] = p1;
}

// all weight splits fused into one launch
__global__ void fused_split_w(const float* __restrict__ Ua,
                              const float* __restrict__ Wa, const float* __restrict__ Whh,
                              const float* __restrict__ ba, const float* __restrict__ bhh,
                              const float* __restrict__ W_ih) {
    const int NU = H_ * H_;
    const int NC = 4 * H_ * H_;
    int i = blockIdx.x * blockDim.x + threadIdx.x;
    if (i < NU) {
        // Ua B-split
        int r = i >> 10, k = i & (H_ - 1);
        __nv_bfloat16 hi, lo; split2(Ua[i], hi, lo);
        size_t base = (size_t)r * K3_;
        g_Ua3[base + k] = hi; g_Ua3[base + H_ + k] = hi; g_Ua3[base + 2 * H_ + k] = lo;
    } else if (i < NU + NC) {
        int j = i - NU;
        int r = j >> 10, k = j & (H_ - 1);
        float v = (r < H_) ? Wa[j] : Whh[j - H_ * H_];
        __nv_bfloat16 hi, lo; split2(v, hi, lo);
        size_t base = (size_t)r * K3_;
        g_Wcat3[base + k] = hi; g_Wcat3[base + H_ + k] = hi; g_Wcat3[base + 2 * H_ + k] = lo;
        if (j < 4 * H_) g_biascat[j] = (j < H_) ? ba[j] : bhh[j - H_];
    } else {
        int j = i - NU - NC;
        int r = j >> 11, c = j & (2 * H_ - 1);
        __nv_bfloat16 hi, lo; split2(W_ih[j], hi, lo);
        if (c < H_) {
            size_t base = (size_t)r * K3_;
            g_Wihx3[base + c] = hi; g_Wihx3[base + H_ + c] = hi; g_Wihx3[base + 2 * H_ + c] = lo;
        } else {
            int c2 = c - H_;
            size_t base = (size_t)r * K3_;
            g_Wihc3[base + c2] = hi; g_Wihc3[base + H_ + c2] = hi; g_Wihc3[base + 2 * H_ + c2] = lo;
        }
    }
}

__global__ void splitA3(const float* __restrict__ src, __nv_bfloat16* __restrict__ dst,
                        int n, int K) {
    int i = blockIdx.x * blockDim.x + threadIdx.x;
    if (i >= n) return;
    int r = i / K, k = i % K;
    __nv_bfloat16 hi, lo; split2(src[i], hi, lo);
    size_t base = (size_t)r * 3 * K;
    dst[base + k] = hi; dst[base + K + k] = lo; dst[base + 2 * K + k] = hi;
}

__global__ void gather_emb3(const int* __restrict__ target, const float* __restrict__ embedding) {
    int i = blockIdx.x * blockDim.x + threadIdx.x;   // 2560*1024
    int row = i >> 10, hh = i & (H_ - 1);
    int b = row / T_, t = row % T_;
    int tok = (t == 0) ? 0 : target[b * T_ + t - 1];
    __nv_bfloat16 hi, lo; split2(embedding[(size_t)tok * H_ + hh], hi, lo);
    size_t base = (size_t)row * K3_;
    g_emb3[base + hh] = hi; g_emb3[base + H_ + hh] = lo; g_emb3[base + 2 * H_ + hh] = hi;
}

__global__ void init_h(const float* __restrict__ eh) {
    int i = blockIdx.x * blockDim.x + threadIdx.x;   // 65536
    int b = i >> 10, hh = i & (H_ - 1);
    float v = eh[i];
    g_h[i] = v;
    __nv_bfloat16 hi, lo; split2(v, hi, lo);
    size_t base = (size_t)b * K3_;
    g_h3[base + hh] = hi; g_h3[base + H_ + hh] = lo; g_h3[base + 2 * H_ + hh] = hi;
}

// ----------------------------- persistent recurrence kernel -------------------
DINLINE void grid_barrier() {
    __syncthreads();
    if (threadIdx.x == 0) {
        __threadfence();                       // publish my writes
        unsigned gen = g_bar_gen;
        if (atomicAdd(&g_bar_cnt, 1) == PGRID - 1) {
            g_bar_cnt = 0;
            __threadfence();
            g_bar_gen = gen + 1;
        } else {
            while (g_bar_gen == gen) {}
        }
        __threadfence();                       // acquire + L1 invalidate
    }
    __syncthreads();
}

__global__ __launch_bounds__(PTHREADS, 1)
void recurrence_persistent(const float* __restrict__ Va, const float* __restrict__ bv,
                           float* __restrict__ out_attn, float* __restrict__ out_hidden)
{
    extern __shared__ char ps[];
    const int tid = threadIdx.x;
    const int warp = tid >> 5, lane = tid & 31;
    const int bid = blockIdx.x;

    for (int t = 0; t < T_; t++) {
        // ================= phase 1: qgh partial GEMM =================
        // job bid: bz = bid>>6 (K-window), bn = (bid&63)*64 (N-tile)
        {
            const int bz = bid >> 6;
            const int bn = (bid & 63) * PBN;
            const int wm = (warp & 1) * 32;          // WARPS_M=2, WM=32
            const int wn = (warp >> 1) * 16;         // WARPS_N=4, WN=16
            __nv_bfloat16* As = (__nv_bfloat16*)ps;
            __nv_bfloat16* Bs = As + PSTG * PBM * PLDSM;
            const __nv_bfloat16* A  = g_h3 + bz * PKW;
            const __nv_bfloat16* Bm = g_Wcat3 + (size_t)bn * K3_ + bz * PKW;

            auto issue = [&](int slot, int kt) {
                const __nv_bfloat16* Ab = A + kt * PBK;
                const __nv_bfloat16* Bb = Bm + kt * PBK;
                __nv_bfloat16* As_s = As + slot * PBM * PLDSM;
                __nv_bfloat16* Bs_s = Bs + slot * PBN * PLDSM;
                #pragma unroll
                for (int v = tid; v < PBM * PBK / 8; v += PTHREADS) {
                    int r = v >> 3, c = (v & 7) * 8;
                    cp_async16(&As_s[r * PLDSM + c], Ab + (size_t)r * K3_ + c);
                }
                #pragma unroll
                for (int v = tid; v < PBN * PBK / 8; v += PTHREADS) {
                    int r = v >> 3, c = (v & 7) * 8;
                    cp_async16(&Bs_s[r * PLDSM + c], Bb + (size_t)r * K3_ + c);
                }
            };

            issue(0, 0); cp_commit();
            issue(1, 1); cp_commit();

            float acc[2][2][4] = {};

            for (int kt = 0; kt < PKT; kt++) {
                cp_wait<1>();
                __syncthreads();
                if (kt + 2 < PKT) issue((kt + 2) % PSTG, kt + 2);
                cp_commit();

                const __nv_bfloat16* As_s = As + (kt % PSTG) * PBM * PLDSM;
                const __nv_bfloat16* Bs_s = Bs + (kt % PSTG) * PBN * PLDSM;

                #pragma unroll
                for (int kk = 0; kk < PBK; kk += 16) {
                    uint32_t af[2][4];
                    #pragma unroll
                    for (int mi = 0; mi < 2; mi++) {
                        int row = wm + mi * 16 + (lane & 15);
                        int col = kk + (lane >> 4) * 8;
                        ldmx4(af[mi][0], af[mi][1], af[mi][2], af[mi][3],
                              smem_u32(&As_s[row * PLDSM + col]));
                    }
                    uint32_t bfr[2][2];
                    #pragma unroll
                    for (int ni = 0; ni < 2; ni++) {
                        int row = wn + ni * 8 + (lane & 7);
                        int col = kk + ((lane >> 3) & 1) * 8;
                        ldmx2(bfr[ni][0], bfr[ni][1], smem_u32(&Bs_s[row * PLDSM + col]));
                    }
                    #pragma unroll
                    for (int mi = 0; mi < 2; mi++)
                        #pragma unroll
                        for (int ni = 0; ni < 2; ni++)
                            mma_bf16(acc[mi][ni][0], acc[mi][ni][1], acc[mi][ni][2], acc[mi][ni][3],
                                     af[mi][0], af[mi][1], af[mi][2], af[mi][3],
                                     bfr[ni][0], bfr[ni][1]);
                }
                __syncthreads();
            }
            cp_wait<0>();

            float* Cp = g_qgh2 + (size_t)bz * B4H_;
            #pragma unroll
            for (int mi = 0; mi < 2; mi++) {
                #pragma unroll
                for (int ni = 0; ni < 2; ni++) {
                    int r0 = wm + mi * 16 + (lane >> 2);
                    int c0 = bn + wn + ni * 8 + (lane & 3) * 2;
                    float b0 = 0.f, b1 = 0.f;
                    if (bz == 0) { b0 = g_biascat[c0]; b1 = g_biascat[c0 + 1]; }
                    Cp[(size_t)r0 * 4096 + c0]           = acc[mi][ni][0] + b0;
                    Cp[(size_t)r0 * 4096 + c0 + 1]       = acc[mi][ni][1] + b1;
                    Cp[(size_t)(r0 + 8) * 4096 + c0]     = acc[mi][ni][2] + b0;
                    Cp[(size_t)(r0 + 8) * 4096 + c0 + 1] = acc[mi][ni][3] + b1;
                }
            }
        }
        grid_barrier();

        // ================= phase 2: attention + GRU (blocks 0..63) ===========
        if (bid < B_) {
            const int b = bid;
            float* s_q  = (float*)ps;              // H floats
            float* s_va = s_q + H_;                // H floats
            float* s_sc = s_va + H_;               // S floats

            // q = sum of 2 K-partials (bias folded into partial 0); __ldcg (L1-safe)
            for (int i = tid; i < H_; i += PTHREADS) {
                float a = __ldcg(g_qgh2 + b * 4 * H_ + i)
                        + __ldcg(g_qgh2 + (size_t)B4H_ + b * 4 * H_ + i);
                s_q[i]  = a;
                s_va[i] = Va[i];
            }
            __syncthreads();

            // scores
            for (int s = warp; s < S_; s += 8) {
                const float4* kr  = (const float4*)(g_keysU + ((size_t)b * S_ + s) * H_);
                const float4* q4p = (const float4*)s_q;
                const float4* v4p = (const float4*)s_va;
                float a = 0.f;
                #pragma unroll 4
                for (int j = lane; j < H_ / 4; j += 32) {
                    float4 k4 = kr[j];
                    float4 q4 = q4p[j];
                    float4 v4 = v4p[j];
                    a += v4.x * fast_tanh(q4.x + k4.x) + v4.y * fast_tanh(q4.y + k4.y)
                       + v4.z * fast_tanh(q4.z + k4.z) + v4.w * fast_tanh(q4.w + k4.w);
                }
                #pragma unroll
                for (int o = 16; o; o >>= 1) a += __shfl_xor_sync(0xffffffffu, a, o);
                if (lane == 0) s_sc[s] = a + bv[0];
            }
            __syncthreads();

            // softmax over S=64 in warp 0
            if (warp == 0) {
                float v0 = s_sc[lane], v1 = s_sc[lane + 32];
                float m = fmaxf(v0, v1);
                #pragma unroll
                for (int o = 16; o; o >>= 1) m = fmaxf(m, __shfl_xor_sync(0xffffffffu, m, o));
                float e0 = __expf(v0 - m), e1 = __expf(v1 - m);
                float ss = e0 + e1;
                #pragma unroll
                for (int o = 16; o; o >>= 1) ss += __shfl_xor_sync(0xffffffffu, ss, o);
                float inv = 1.f / ss;
                s_sc[lane] = e0 * inv;
                s_sc[lane + 32] = e1 * inv;
            }
            __syncthreads();

            if (tid < S_) out_attn[((size_t)b * T_ + t) * S_ + tid] = s_sc[tid];

            // gi_c contraction + GRU, 4 consecutive h per thread
            const int hh = tid * 4;
            float4 gcr = make_float4(0.f, 0.f, 0.f, 0.f);
            float4 gcz = make_float4(0.f, 0.f, 0.f, 0.f);
            float4 gcn = make_float4(0.f, 0.f, 0.f, 0.f);
            const float* base = g_encWc + (size_t)b * S_ * 3 * H_;
            #pragma unroll 4
            for (int s = 0; s < S_; s++) {
                float w = s_sc[s];
                const float* row = base + (size_t)s * 3 * H_;
                float4 r4 = *(const float4*)(row + hh);
                float4 z4 = *(const float4*)(row + H_ + hh);
                float4 n4 = *(const float4*)(row + 2 * H_ + hh);
                gcr.x += w * r4.x; gcr.y += w * r4.y; gcr.z += w * r4.z; gcr.w += w * r4.w;
                gcz.x += w * z4.x; gcz.y += w * z4.y; gcz.z += w * z4.z; gcz.w += w * z4.w;
                gcn.x += w * n4.x; gcn.y += w * n4.y; gcn.z += w * n4.z; gcn.w += w * n4.w;
            }

            float4 ghr = make_float4(0.f, 0.f, 0.f, 0.f);
            float4 ghz = make_float4(0.f, 0.f, 0.f, 0.f);
            float4 ghn = make_float4(0.f, 0.f, 0.f, 0.f);
            #pragma unroll
            for (int z = 0; z < PNZ; z++) {
                const float* gp = g_qgh2 + (size_t)z * B4H_ + b * 4 * H_ + H_;
                float4 a = __ldcg((const float4*)(gp + hh));
                float4 c = __ldcg((const float4*)(gp + H_ + hh));
                float4 d = __ldcg((const float4*)(gp + 2 * H_ + hh));
                ghr.x += a.x; ghr.y += a.y; ghr.z += a.z; ghr.w += a.w;
                ghz.x += c.x; ghz.y += c.y; ghz.z += c.z; ghz.w += c.w;
                ghn.x += d.x; ghn.y += d.y; ghn.z += d.z; ghn.w += d.w;
            }

            const float* gi = g_gix + (size_t)(b * T_ + t) * 3 * H_;
            float4 gir = *(const float4*)(gi + hh);
            float4 giz = *(const float4*)(gi + H_ + hh);
            float4 gin = *(const float4*)(gi + 2 * H_ + hh);
            float4 hp  = *(const float4*)(g_h + b * H_ + hh);

            float hn4[4];
            #pragma unroll
            for (int q = 0; q < 4; q++) {
                float ir  = ((&gir.x)[q]) + ((&gcr.x)[q]);
                float iz  = ((&giz.x)[q]) + ((&gcz.x)[q]);
                float in_ = ((&gin.x)[q]) + ((&gcn.x)[q]);
                float hr = ((&ghr.x)[q]), hz = ((&ghz.x)[q]), hnn = ((&ghn.x)[q]);
                float r = 1.f / (1.f + expf(-(ir + hr)));
                float z = 1.f / (1.f + expf(-(iz + hz)));
                float n = tanhf(in_ + r * hnn);
                hn4[q] = (1.f - z) * n + z * ((&hp.x)[q]);
            }

            *(float4*)(g_h + b * H_ + hh) = make_float4(hn4[0], hn4[1], hn4[2], hn4[3]);

            __nv_bfloat16 hi[4], lo[4];
            #pragma unroll
            for (int q = 0; q < 4; q++) split2(hn4[q], hi[q], lo[q]);
            __nv_bfloat162 hi01(hi[0], hi[1]), hi23(hi[2], hi[3]);
            __nv_bfloat162 lo01(lo[0], lo[1]), lo23(lo[2], lo[3]);
            size_t b3 = (size_t)b * K3_;
            *(__nv_bfloat162*)&g_h3[b3 + hh]              = hi01;
            *(__nv_bfloat162*)&g_h3[b3 + hh + 2]          = hi23;
            *(__nv_bfloat162*)&g_h3[b3 + H_ + hh]         = lo01;
            *(__nv_bfloat162*)&g_h3[b3 + H_ + hh + 2]     = lo23;
            *(__nv_bfloat162*)&g_h3[b3 + 2 * H_ + hh]     = hi01;
            *(__nv_bfloat162*)&g_h3[b3 + 2 * H_ + hh + 2] = hi23;
            size_t hall = (size_t)(b * T_ + t) * H_ + hh;
            *(__nv_bfloat162*)&g_Hall_b[hall]     = hi01;
            *(__nv_bfloat162*)&g_Hall_b[hall + 2] = hi23;
            if (t == T_ - 1)
                *(float4*)(out_hidden + b * H_ + hh) =
                    make_float4(hn4[0], hn4[1], hn4[2], hn4[3]);
        }
        grid_barrier();
    }
}

// ----------------------------- online log-softmax (in place) ------------------
__global__ __launch_bounds__(512)
void logsoftmax_kernel(float* __restrict__ x)
{
    __shared__ float sm[16], ss[16];
    float* p = x + (size_t)blockIdx.x * V_;
    const int tid = threadIdx.x;

    float m = -1e30f, sacc = 0.f;
    for (int i = tid; i < V_ / 4; i += 512) {
        float4 v = ((const float4*)p)[i];
        #pragma unroll
        for (int q = 0; q < 4; q++) {
            float xv = (&v.x)[q];
            if (xv > m) { sacc = sacc * __expf(m - xv) + 1.f; m = xv; }
            else        { sacc += __expf(xv - m); }
        }
    }
    #pragma unroll
    for (int o = 16; o; o >>= 1) {
        float m2 = __shfl_xor_sync(0xffffffffu, m, o);
        float s2 = __shfl_xor_sync(0xffffffffu, sacc, o);
        if (m2 > m) { sacc = sacc * __expf(m - m2) + s2; m = m2; }
        else        { sacc += s2 * __expf(m2 - m); }
    }
    if ((tid & 31) == 0) { sm[tid >> 5] = m; ss[tid >> 5] = sacc; }
    __syncthreads();
    if (tid == 0) {
        float M = sm[0], Sv = ss[0];
        #pragma unroll
        for (int w = 1; w < 16; w++) {
            float m2 = sm[w], s2 = ss[w];
            if (m2 > M) { Sv = Sv * __expf(M - m2) + s2; M = m2; }
            else        { Sv += s2 * __expf(m2 - M); }
        }
        sm[0] = M + logf(Sv);
    }
    __syncthreads();
    float lse = sm[0];
    for (int i = tid; i < V_ / 4; i += 512) {
        float4 v = ((const float4*)p)[i];
        v.x -= lse; v.y -= lse; v.z -= lse; v.w -= lse;
        ((float4*)p)[i] = v;
    }
}

// ----------------------------- host launcher ----------------------------------
template <typename Tp>
static Tp* sym_addr(const void* sym) {
    void* p = nullptr;
    cudaGetSymbolAddress(&p, sym);
    return (Tp*)p;
}

#define BIG_CFG  128, 128, 64, 64, 32, 3
static constexpr int SMEM_BIG = 3 * (128 + 128) * (64 + 8) * 2;  // 110592

extern "C" void kernel_launch(void* const* d_in, const int* in_sizes, int n_in,
                              void* d_out, int out_size)
{
    const float* enc       = (const float*)d_in[0];
    const float* ehid      = (const float*)d_in[1];
    const int*   target    = (const int*)d_in[2];
    const float* embedding = (const float*)d_in[3];
    const float* Wa        = (const float*)d_in[4];
    const float* ba        = (const float*)d_in[5];
    const float* Ua        = (const float*)d_in[6];
    const float* bu        = (const float*)d_in[7];
    const float* Va        = (const float*)d_in[8];
    const float* bv        = (const float*)d_in[9];
    const float* W_ih      = (const float*)d_in[10];
    const float* W_hh      = (const float*)d_in[11];
    const float* b_ih      = (const float*)d_in[12];
    const float* b_hh      = (const float*)d_in[13];
    const float* W_out     = (const float*)d_in[14];
    const float* b_out     = (const float*)d_in[15];

    float* out      = (float*)d_out;
    float* out_dec  = out;                                    // [B,T,V]
    float* out_hid  = out + (size_t)B_ * T_ * V_;             // [1,B,H]
    float* out_attn = out_hid + (size_t)B_ * H_;              // [B,T,S]

    __nv_bfloat16* p_Wout  = sym_addr<__nv_bfloat16>(g_Wout_b);
    __nv_bfloat16* p_Ua3   = sym_addr<__nv_bfloat16>(g_Ua3);
    __nv_bfloat16* p_Wihx3 = sym_addr<__nv_bfloat16>(g_Wihx3);
    __nv_bfloat16* p_Wihc3 = sym_addr<__nv_bfloat16>(g_Wihc3);
    __nv_bfloat16* p_enc3  = sym_addr<__nv_bfloat16>(g_enc3);
    __nv_bfloat16* p_emb3  = sym_addr<__nv_bfloat16>(g_emb3);
    __nv_bfloat16* p_Hall  = sym_addr<__nv_bfloat16>(g_Hall_b);
    float* p_keysU = sym_addr<float>(g_keysU);
    float* p_encWc = sym_addr<float>(g_encWc);
    float* p_gix   = sym_addr<float>(g_gix);

    cudaFuncSetAttribute(gemm_tn_pipe<BIG_CFG>,
                         cudaFuncAttributeMaxDynamicSharedMemorySize, SMEM_BIG);
    cudaFuncSetAttribute(recurrence_persistent,
                         cudaFuncAttributeMaxDynamicSharedMemorySize, PSMEM);

    // ---- prep (5 launches so launch #6 = first big GEMM for ncu) ----
    conv_f2b_v4<<<(V_ * H_ / 4 + 255) / 256, 256>>>(W_out, p_Wout, V_ * H_ / 4);
    {
        int total = H_ * H_ + 4 * H_ * H_ + 3 * H_ * 2 * H_;
        fused_split_w<<<total / 256, 256>>>(Ua, Wa, W_hh, ba, b_hh, W_ih);
    }
    splitA3<<<(B_ * S_ * H_) / 256, 256>>>(enc, p_enc3, B_ * S_ * H_, H_);
    gather_emb3<<<(B_ * T_ * H_) / 256, 256>>>(target, embedding);
    init_h<<<(B_ * H_) / 256, 256>>>(ehid);

    // keysU = enc @ Ua^T + bu : [4096, 1024], split K=3072
    {
        dim3 grid(H_ / 128, (B_ * S_) / 128, 1);
        gemm_tn_pipe<BIG_CFG><<<grid, 256, SMEM_BIG>>>(
            p_enc3, K3_, p_Ua3, K3_, bu, p_keysU, H_, B_ * S_, H_, K3_);
    }
    // gi_x = emb @ W_ihx^T + b_ih : [2560, 3072], split K=3072
    {
        dim3 grid((3 * H_) / 128, (B_ * T_) / 128, 1);
        gemm_tn_pipe<BIG_CFG><<<grid, 256, SMEM_BIG>>>(
            p_emb3, K3_, p_Wihx3, K3_, b_ih, p_gix, 3 * H_, B_ * T_, 3 * H_, K3_);
    }
    // encWc = enc @ W_ihc^T : [4096, 3072], split K=3072
    {
        dim3 grid((3 * H_) / 128, (B_ * S_) / 128, 1);
        gemm_tn_pipe<BIG_CFG><<<grid, 256, SMEM_BIG>>>(
            p_enc3, K3_, p_Wihc3, K3_, nullptr, p_encWc, 3 * H_, B_ * S_, 3 * H_, K3_);
    }

    // ---- full recurrence: ONE persistent launch ----
    recurrence_persistent<<<PGRID, PTHREADS, PSMEM>>>(Va, bv, out_attn, out_hid);

    // ---- output projection + log-softmax ----
    {
        dim3 grid(V_ / 128, (B_ * T_) / 128, 1);
        gemm_tn_pipe<BIG_CFG><<<grid, 256, SMEM_BIG>>>(
            p_Hall, H_, p_Wout, H_, b_out, out_dec, V_, B_ * T_, V_, H_);
    }
    logsoftmax_kernel<<<B_ * T_, 512>>>(out_dec);
}